// round 1
// baseline (speedup 1.0000x reference)
#include <cuda_runtime.h>
#include <cstdint>
#include <cstddef>

#define TT_T 256      // tokens
#define HH 1024       // hidden
#define EE 256        // experts
#define II 256        // intermediate
#define NPAIR 2048    // T * top_k
#define HC 256        // h-chunk staged in smem for mlp1

typedef unsigned long long u64;

// ---------------- scratch (device globals; no allocations allowed) ----------------
__device__ float g_scores[TT_T * EE];        // sigmoid(logits)
__device__ int   g_cnt[EE];
__device__ int   g_base[EE];
__device__ int   g_pair_tok[NPAIR];
__device__ float g_pair_w[NPAIR];
__device__ float g_act[NPAIR * II];          // routed silu(h1)*h3
__device__ float g_act_sh[TT_T * II];        // shared-expert silu(h1)*h3

// ---------------- f32x2 helpers ----------------
__device__ __forceinline__ u64 fma2(u64 a, u64 b, u64 c) {
    u64 d;
    asm("fma.rn.f32x2 %0, %1, %2, %3;" : "=l"(d) : "l"(a), "l"(b), "l"(c));
    return d;
}
__device__ __forceinline__ u64 pack2(float x, float y) {
    u64 r;
    asm("mov.b64 %0, {%1, %2};" : "=l"(r) : "f"(x), "f"(y));
    return r;
}
__device__ __forceinline__ float2 unpack2(u64 v) {
    float2 r;
    asm("mov.b64 {%0, %1}, %2;" : "=f"(r.x), "=f"(r.y) : "l"(v));
    return r;
}

// ---------------- kernel: zero output ----------------
__global__ void k_zero(float* __restrict__ out, int n) {
    int i = blockIdx.x * blockDim.x + threadIdx.x;
    if (i < n) out[i] = 0.f;
}

// ---------------- kernel: gate scores = sigmoid(x @ gate_w^T) ----------------
// grid 256 blocks: eg = b & 31 (8 experts each), tg = b >> 5 (32 tokens each), 256 thr
__global__ void k_gate(const float* __restrict__ x, const float* __restrict__ gw) {
    __shared__ float gws[8 * HH];
    int eg = blockIdx.x & 31;
    int tg = blockIdx.x >> 5;
    int tid = threadIdx.x;
    for (int idx = tid; idx < 8 * HH; idx += 256)
        gws[idx] = gw[eg * 8 * HH + idx];
    __syncthreads();
    int warp = tid >> 5, lane = tid & 31;
    for (int tt = warp; tt < 32; tt += 8) {
        int t = tg * 32 + tt;
        float acc[8];
#pragma unroll
        for (int e = 0; e < 8; e++) acc[e] = 0.f;
        for (int h = lane; h < HH; h += 32) {
            float xv = x[t * HH + h];
#pragma unroll
            for (int e = 0; e < 8; e++) acc[e] += xv * gws[e * HH + h];
        }
#pragma unroll
        for (int e = 0; e < 8; e++) {
            float v = acc[e];
#pragma unroll
            for (int s = 16; s > 0; s >>= 1) v += __shfl_xor_sync(0xffffffffu, v, s);
            if (lane == e)
                g_scores[t * EE + eg * 8 + e] = 1.f / (1.f + __expf(-v));
        }
    }
}

// ---------------- kernel: routing (1 block, thread = token) ----------------
__global__ void k_route(const float* __restrict__ e_bias) {
    int t = threadIdx.x;
    __shared__ float s_bias[EE];
    __shared__ int s_cnt[EE];
    __shared__ int s_ofs[EE];
    s_bias[t] = e_bias[t];
    s_cnt[t] = 0;
    __syncthreads();
    const float* srow = g_scores + t * EE;

    // group scores = sum of top-2 corrected scores per group
    float gsum[8];
#pragma unroll
    for (int g = 0; g < 8; g++) {
        float m1 = -1e30f, m2 = -1e30f;
        for (int j = 0; j < 32; j++) {
            float v = srow[g * 32 + j] + s_bias[g * 32 + j];
            if (v > m1) { m2 = m1; m1 = v; }
            else if (v > m2) { m2 = v; }
        }
        gsum[g] = m1 + m2;
    }
    // top-4 groups (strict >, lowest index wins ties -> matches lax.top_k)
    unsigned gmask = 0;
    for (int it = 0; it < 4; it++) {
        float best = -1e30f; int bi = 0;
#pragma unroll
        for (int g = 0; g < 8; g++)
            if (!((gmask >> g) & 1u) && gsum[g] > best) { best = gsum[g]; bi = g; }
        gmask |= 1u << bi;
    }
    // top-8 experts among selected groups: branchless register insertion sort
    float bv[8]; int bidx[8];
#pragma unroll
    for (int k = 0; k < 8; k++) { bv[k] = -1e30f; bidx[k] = -1; }
    for (int g = 0; g < 8; g++) {
        if (!((gmask >> g) & 1u)) continue;
        for (int j = 0; j < 32; j++) {
            int e = g * 32 + j;
            float v = srow[e] + s_bias[e];
            if (v > bv[7]) {
#pragma unroll
                for (int k = 7; k > 0; k--) {
                    bool sh = v > bv[k - 1];
                    bool ins = (v > bv[k]) && !sh;
                    float nv = sh ? bv[k - 1] : (ins ? v : bv[k]);
                    int   ni = sh ? bidx[k - 1] : (ins ? e : bidx[k]);
                    bv[k] = nv; bidx[k] = ni;
                }
                if (v > bv[0]) { bv[0] = v; bidx[0] = e; }
            }
        }
    }
    // weights from RAW sigmoid scores, normalized, * 2.5
    float w[8]; float wsum = 0.f;
#pragma unroll
    for (int k = 0; k < 8; k++) { w[k] = srow[bidx[k]]; wsum += w[k]; }
    float scl = 2.5f / (wsum + 1e-20f);
#pragma unroll
    for (int k = 0; k < 8; k++) {
        w[k] *= scl;
        atomicAdd(&s_cnt[bidx[k]], 1);
    }
    __syncthreads();
    // prefix sum over expert counts (thread index doubles as expert index)
    int base = 0;
    for (int e = 0; e < t; e++) base += s_cnt[e];
    s_ofs[t] = base;
    g_base[t] = base;
    g_cnt[t] = s_cnt[t];
    __syncthreads();
#pragma unroll
    for (int k = 0; k < 8; k++) {
        int slot = atomicAdd(&s_ofs[bidx[k]], 1);
        g_pair_tok[slot] = t;
        g_pair_w[slot] = w[k];
    }
}

// ---------------- mlp1 tile: gate/up GEMM + silu*up, f32x2 packed over i ----------------
// 128 threads; thread tid owns i-pair (2*tid, 2*tid+1). Weights streamed once.
template <int TT>
__device__ __forceinline__ void mlp1_tile(
    const float* __restrict__ x,
    const float* __restrict__ wg, const float* __restrict__ wu,
    const int* s_toks, int nt, float* __restrict__ act_base, u64* xs)
{
    const int tid = threadIdx.x;
    u64 ag[TT], au[TT];
#pragma unroll
    for (int t2 = 0; t2 < TT; t2++) { ag[t2] = 0ull; au[t2] = 0ull; }
    const float2* wg2 = (const float2*)wg;
    const float2* wu2 = (const float2*)wu;

    for (int h0 = 0; h0 < HH; h0 += HC) {
        __syncthreads();
        // stage x chunk as duplicated f32x2 (coalesced gmem reads along h)
        for (int idx = tid; idx < TT * HC; idx += 128) {
            int t2 = idx / HC;
            int h = idx - t2 * HC;
            float v = (t2 < nt) ? __ldg(&x[s_toks[t2] * HH + h0 + h]) : 0.f;
            xs[t2 * HC + h] = pack2(v, v);
        }
        __syncthreads();
#pragma unroll 1
        for (int h = 0; h < HC; h += 8) {
            float2 wa[8], wb[8];
#pragma unroll
            for (int u = 0; u < 8; u++) {
                wa[u] = wg2[(size_t)(h0 + h + u) * (II / 2) + tid];
                wb[u] = wu2[(size_t)(h0 + h + u) * (II / 2) + tid];
            }
#pragma unroll
            for (int u = 0; u < 8; u++) {
                u64 wgp = pack2(wa[u].x, wa[u].y);
                u64 wup = pack2(wb[u].x, wb[u].y);
#pragma unroll
                for (int t2 = 0; t2 < TT; t2++) {
                    u64 xv = xs[t2 * HC + h + u];
                    ag[t2] = fma2(xv, wgp, ag[t2]);
                    au[t2] = fma2(xv, wup, au[t2]);
                }
            }
        }
    }
#pragma unroll
    for (int t2 = 0; t2 < TT; t2++) {
        if (t2 < nt) {
            float2 g = unpack2(ag[t2]);
            float2 u = unpack2(au[t2]);
            float a0 = g.x / (1.f + __expf(-g.x)) * u.x;
            float a1 = g.y / (1.f + __expf(-g.y)) * u.y;
            *(float2*)(act_base + (size_t)t2 * II + 2 * tid) = make_float2(a0, a1);
        }
    }
}

// grid.x = 256 routed experts + 16 shared-expert token tiles; 128 threads
__global__ void __launch_bounds__(128) k_mlp1(
    const float* __restrict__ x,
    const float* __restrict__ wgate, const float* __restrict__ wup,
    const float* __restrict__ swg, const float* __restrict__ swu)
{
    __shared__ u64 xs[16 * HC];     // 32 KB
    __shared__ int s_toks[16];
    int b = blockIdx.x;
    if (b < EE) {
        int cnt = g_cnt[b];
        int base = g_base[b];
        const float* wg = wgate + (size_t)b * HH * II;
        const float* wu = wup + (size_t)b * HH * II;
        for (int off = 0; off < cnt; off += 16) {
            int nt = min(cnt - off, 16);
            __syncthreads();
            if (threadIdx.x < nt)
                s_toks[threadIdx.x] = g_pair_tok[base + off + threadIdx.x];
            float* act_base = g_act + (size_t)(base + off) * II;
            if (nt <= 8) mlp1_tile<8>(x, wg, wu, s_toks, nt, act_base, xs);
            else         mlp1_tile<16>(x, wg, wu, s_toks, nt, act_base, xs);
        }
    } else {
        int j = b - EE;
        if (threadIdx.x < 16) s_toks[threadIdx.x] = j * 16 + threadIdx.x;
        mlp1_tile<16>(x, swg, swu, s_toks, 16, g_act_sh + (size_t)j * 16 * II, xs);
    }
}

// ---------------- down tile: act @ w_down, atomic accumulate into out ----------------
// 128 threads; thread tid owns h-pair (h0+2*tid, +1). Weights streamed once per chunk.
template <int TT>
__device__ __forceinline__ void down_tile(
    const float* __restrict__ wd, int h0,
    const int* s_toks, const float* s_w, int nt,
    float* __restrict__ out, const u64* acts)
{
    const int tid = threadIdx.x;
    u64 acc[TT];
#pragma unroll
    for (int t2 = 0; t2 < TT; t2++) acc[t2] = 0ull;
    const float2* wd2 = (const float2*)wd;
    const int hp = h0 / 2 + tid;
#pragma unroll 1
    for (int i = 0; i < II; i += 8) {
        float2 wv[8];
#pragma unroll
        for (int u = 0; u < 8; u++)
            wv[u] = wd2[(size_t)(i + u) * (HH / 2) + hp];
#pragma unroll
        for (int u = 0; u < 8; u++) {
            u64 wp = pack2(wv[u].x, wv[u].y);
#pragma unroll
            for (int t2 = 0; t2 < TT; t2++)
                acc[t2] = fma2(acts[t2 * II + i + u], wp, acc[t2]);
        }
    }
#pragma unroll
    for (int t2 = 0; t2 < TT; t2++) {
        if (t2 < nt) {
            float2 r = unpack2(acc[t2]);
            float w = s_w[t2];
            int tok = s_toks[t2];
            atomicAdd(out + (size_t)tok * HH + h0 + 2 * tid,     w * r.x);
            atomicAdd(out + (size_t)tok * HH + h0 + 2 * tid + 1, w * r.y);
        }
    }
}

// grid: (256 routed experts + 16 shared tiles) x 4 h-chunks; 128 threads
__global__ void __launch_bounds__(128) k_down(
    const float* __restrict__ wdown, const float* __restrict__ swd,
    float* __restrict__ out)
{
    __shared__ u64 acts[16 * II];   // 32 KB
    __shared__ int s_toks[16];
    __shared__ float s_w[16];
    int b = blockIdx.x;
    int h0 = blockIdx.y * 256;
    if (b < EE) {
        int cnt = g_cnt[b];
        int base = g_base[b];
        const float* wd = wdown + (size_t)b * II * HH;
        for (int off = 0; off < cnt; off += 16) {
            int nt = min(cnt - off, 16);
            __syncthreads();
            if (threadIdx.x < nt) {
                s_toks[threadIdx.x] = g_pair_tok[base + off + threadIdx.x];
                s_w[threadIdx.x]   = g_pair_w[base + off + threadIdx.x];
            }
            for (int idx = threadIdx.x; idx < 16 * II; idx += 128) {
                int t2 = idx >> 8, i = idx & 255;
                float v = (t2 < nt) ? g_act[(size_t)(base + off + t2) * II + i] : 0.f;
                acts[idx] = pack2(v, v);
            }
            __syncthreads();
            if (nt <= 8) down_tile<8>(wd, h0, s_toks, s_w, nt, out, acts);
            else         down_tile<16>(wd, h0, s_toks, s_w, nt, out, acts);
        }
    } else {
        int j = b - EE;
        if (threadIdx.x < 16) {
            s_toks[threadIdx.x] = j * 16 + threadIdx.x;
            s_w[threadIdx.x] = 1.0f;
        }
        for (int idx = threadIdx.x; idx < 16 * II; idx += 128) {
            int t2 = idx >> 8, i = idx & 255;
            float v = g_act_sh[(size_t)(j * 16 + t2) * II + i];
            acts[idx] = pack2(v, v);
        }
        __syncthreads();
        down_tile<16>(swd, h0, s_toks, s_w, 16, out, acts);
    }
}

// ---------------- launch ----------------
extern "C" void kernel_launch(void* const* d_in, const int* in_sizes, int n_in,
                              void* d_out, int out_size)
{
    const float* x       = (const float*)d_in[0];  // [1,1,T,H]
    const float* gate_w  = (const float*)d_in[1];  // [E,H]
    const float* e_bias  = (const float*)d_in[2];  // [E]
    const float* w_gate  = (const float*)d_in[3];  // [E,H,I]
    const float* w_up    = (const float*)d_in[4];  // [E,H,I]
    const float* w_down  = (const float*)d_in[5];  // [E,I,H]
    const float* sw_gate = (const float*)d_in[6];  // [H,I]
    const float* sw_up   = (const float*)d_in[7];  // [H,I]
    const float* sw_down = (const float*)d_in[8];  // [I,H]
    float* out = (float*)d_out;                    // [1,1,T,H] fp32

    k_zero<<<(TT_T * HH + 255) / 256, 256>>>(out, TT_T * HH);
    k_gate<<<256, 256>>>(x, gate_w);
    k_route<<<1, 256>>>(e_bias);
    k_mlp1<<<EE + 16, 128>>>(x, w_gate, w_up, sw_gate, sw_up);
    k_down<<<dim3(EE + 16, 4), 128>>>(w_down, sw_down, out);
}

// round 2
// speedup vs baseline: 2.4557x; 2.4557x over previous
#include <cuda_runtime.h>
#include <cstdint>
#include <cstddef>

#define TT_T 256      // tokens
#define HH 1024       // hidden
#define EE 256        // experts
#define II 256        // intermediate
#define NPAIR 2048    // T * top_k
#define HC 256        // h-chunk staged in smem for mlp1

typedef unsigned long long u64;

// ---------------- scratch (device globals; no allocations allowed) ----------------
__device__ float g_scores[TT_T * EE];        // sigmoid(logits)
__device__ int   g_cnt[EE];
__device__ int   g_base[EE];
__device__ int   g_pair_tok[NPAIR];
__device__ float g_pair_w[NPAIR];
__device__ float g_act[NPAIR * II];          // routed silu(h1)*h3
__device__ float g_act_sh[TT_T * II];        // shared-expert silu(h1)*h3

// ---------------- f32x2 helpers ----------------
__device__ __forceinline__ u64 fma2(u64 a, u64 b, u64 c) {
    u64 d;
    asm("fma.rn.f32x2 %0, %1, %2, %3;" : "=l"(d) : "l"(a), "l"(b), "l"(c));
    return d;
}
__device__ __forceinline__ u64 add2(u64 a, u64 b) {
    u64 d;
    asm("add.rn.f32x2 %0, %1, %2;" : "=l"(d) : "l"(a), "l"(b));
    return d;
}
__device__ __forceinline__ u64 pack2(float x, float y) {
    u64 r;
    asm("mov.b64 %0, {%1, %2};" : "=l"(r) : "f"(x), "f"(y));
    return r;
}
__device__ __forceinline__ float2 unpack2(u64 v) {
    float2 r;
    asm("mov.b64 {%0, %1}, %2;" : "=f"(r.x), "=f"(r.y) : "l"(v));
    return r;
}

// ---------------- kernel: zero output ----------------
__global__ void k_zero(float* __restrict__ out, int n) {
    int i = blockIdx.x * blockDim.x + threadIdx.x;
    if (i < n) out[i] = 0.f;
}

// ---------------- kernel: gate scores = sigmoid(x @ gate_w^T) ----------------
__global__ void k_gate(const float* __restrict__ x, const float* __restrict__ gw) {
    __shared__ float gws[8 * HH];
    int eg = blockIdx.x & 31;
    int tg = blockIdx.x >> 5;
    int tid = threadIdx.x;
    for (int idx = tid; idx < 8 * HH; idx += 256)
        gws[idx] = gw[eg * 8 * HH + idx];
    __syncthreads();
    int warp = tid >> 5, lane = tid & 31;
    for (int tt = warp; tt < 32; tt += 8) {
        int t = tg * 32 + tt;
        float acc[8];
#pragma unroll
        for (int e = 0; e < 8; e++) acc[e] = 0.f;
        for (int h = lane; h < HH; h += 32) {
            float xv = x[t * HH + h];
#pragma unroll
            for (int e = 0; e < 8; e++) acc[e] += xv * gws[e * HH + h];
        }
#pragma unroll
        for (int e = 0; e < 8; e++) {
            float v = acc[e];
#pragma unroll
            for (int s = 16; s > 0; s >>= 1) v += __shfl_xor_sync(0xffffffffu, v, s);
            if (lane == e)
                g_scores[t * EE + eg * 8 + e] = 1.f / (1.f + __expf(-v));
        }
    }
}

// ---------------- kernel: routing (1 block, thread = token) ----------------
__global__ void k_route(const float* __restrict__ e_bias) {
    int t = threadIdx.x;
    __shared__ float s_bias[EE];
    __shared__ int s_cnt[EE];
    __shared__ int s_ofs[EE];
    s_bias[t] = e_bias[t];
    s_cnt[t] = 0;
    __syncthreads();
    const float* srow = g_scores + t * EE;

    float gsum[8];
#pragma unroll
    for (int g = 0; g < 8; g++) {
        float m1 = -1e30f, m2 = -1e30f;
        for (int j = 0; j < 32; j++) {
            float v = srow[g * 32 + j] + s_bias[g * 32 + j];
            if (v > m1) { m2 = m1; m1 = v; }
            else if (v > m2) { m2 = v; }
        }
        gsum[g] = m1 + m2;
    }
    unsigned gmask = 0;
    for (int it = 0; it < 4; it++) {
        float best = -1e30f; int bi = 0;
#pragma unroll
        for (int g = 0; g < 8; g++)
            if (!((gmask >> g) & 1u) && gsum[g] > best) { best = gsum[g]; bi = g; }
        gmask |= 1u << bi;
    }
    float bv[8]; int bidx[8];
#pragma unroll
    for (int k = 0; k < 8; k++) { bv[k] = -1e30f; bidx[k] = -1; }
    for (int g = 0; g < 8; g++) {
        if (!((gmask >> g) & 1u)) continue;
        for (int j = 0; j < 32; j++) {
            int e = g * 32 + j;
            float v = srow[e] + s_bias[e];
            if (v > bv[7]) {
#pragma unroll
                for (int k = 7; k > 0; k--) {
                    bool sh = v > bv[k - 1];
                    bool ins = (v > bv[k]) && !sh;
                    float nv = sh ? bv[k - 1] : (ins ? v : bv[k]);
                    int   ni = sh ? bidx[k - 1] : (ins ? e : bidx[k]);
                    bv[k] = nv; bidx[k] = ni;
                }
                if (v > bv[0]) { bv[0] = v; bidx[0] = e; }
            }
        }
    }
    float w[8]; float wsum = 0.f;
#pragma unroll
    for (int k = 0; k < 8; k++) { w[k] = srow[bidx[k]]; wsum += w[k]; }
    float scl = 2.5f / (wsum + 1e-20f);
#pragma unroll
    for (int k = 0; k < 8; k++) {
        w[k] *= scl;
        atomicAdd(&s_cnt[bidx[k]], 1);
    }
    __syncthreads();
    int base = 0;
    for (int e = 0; e < t; e++) base += s_cnt[e];
    s_ofs[t] = base;
    g_base[t] = base;
    g_cnt[t] = s_cnt[t];
    __syncthreads();
#pragma unroll
    for (int k = 0; k < 8; k++) {
        int slot = atomicAdd(&s_ofs[bidx[k]], 1);
        g_pair_tok[slot] = t;
        g_pair_w[slot] = w[k];
    }
}

// ---------------- mlp1 tile v2 ----------------
// 256 threads: ip = tid&63 (i-pair within this 128-col half), hs = tid>>6 (4 h-slices)
// Each thread accumulates over h strided; cross-slice reduce via smem at the end.
template <int TT>
__device__ __forceinline__ void mlp1_tile(
    const float* __restrict__ x,
    const float* __restrict__ wg, const float* __restrict__ wu,
    const int* s_toks, int nt, float* __restrict__ act_base, u64* xs, int ih)
{
    const int tid = threadIdx.x;
    const int ip = tid & 63;
    const int hs = tid >> 6;
    const int ipg = ih * 64 + ip;           // global i-pair 0..127
    u64 ag[TT], au[TT];
#pragma unroll
    for (int t2 = 0; t2 < TT; t2++) { ag[t2] = 0ull; au[t2] = 0ull; }
    const float2* wg2 = (const float2*)wg;
    const float2* wu2 = (const float2*)wu;

    for (int h0 = 0; h0 < HH; h0 += HC) {
        __syncthreads();
        for (int idx = tid; idx < TT * HC; idx += 256) {
            int t2 = idx / HC;
            int h = idx - t2 * HC;
            float v = (t2 < nt) ? __ldg(&x[s_toks[t2] * HH + h0 + h]) : 0.f;
            xs[t2 * HC + h] = pack2(v, v);
        }
        __syncthreads();
#pragma unroll 1
        for (int h = hs * 4; h < HC; h += 16) {
            float2 wa[4], wb[4];
#pragma unroll
            for (int u = 0; u < 4; u++) {
                wa[u] = wg2[(size_t)(h0 + h + u) * (II / 2) + ipg];
                wb[u] = wu2[(size_t)(h0 + h + u) * (II / 2) + ipg];
            }
#pragma unroll
            for (int u = 0; u < 4; u++) {
                u64 wgp = pack2(wa[u].x, wa[u].y);
                u64 wup = pack2(wb[u].x, wb[u].y);
#pragma unroll
                for (int t2 = 0; t2 < TT; t2++) {
                    u64 xv = xs[t2 * HC + h + u];
                    ag[t2] = fma2(xv, wgp, ag[t2]);
                    au[t2] = fma2(xv, wup, au[t2]);
                }
            }
        }
    }
    // cross-slice reduction (conflict-free layout: [t2*256 + hs*64 + ip])
    __syncthreads();
#pragma unroll
    for (int t2 = 0; t2 < TT; t2++) xs[t2 * 256 + hs * 64 + ip] = ag[t2];
    __syncthreads();
    if (hs == 0) {
#pragma unroll
        for (int t2 = 0; t2 < TT; t2++) {
            u64 s = xs[t2 * 256 + ip];
            s = add2(s, xs[t2 * 256 + 64 + ip]);
            s = add2(s, xs[t2 * 256 + 128 + ip]);
            ag[t2] = add2(s, xs[t2 * 256 + 192 + ip]);
        }
    }
    __syncthreads();
#pragma unroll
    for (int t2 = 0; t2 < TT; t2++) xs[t2 * 256 + hs * 64 + ip] = au[t2];
    __syncthreads();
    if (hs == 0) {
#pragma unroll
        for (int t2 = 0; t2 < TT; t2++) {
            if (t2 < nt) {
                u64 s = xs[t2 * 256 + ip];
                s = add2(s, xs[t2 * 256 + 64 + ip]);
                s = add2(s, xs[t2 * 256 + 128 + ip]);
                s = add2(s, xs[t2 * 256 + 192 + ip]);
                float2 g = unpack2(ag[t2]);
                float2 u = unpack2(s);
                float a0 = g.x / (1.f + __expf(-g.x)) * u.x;
                float a1 = g.y / (1.f + __expf(-g.y)) * u.y;
                *(float2*)(act_base + (size_t)t2 * II + 2 * ipg) = make_float2(a0, a1);
            }
        }
    }
}

// grid.x = EE*2 (expert, i-half) + 32 shared-expert (tile, i-half); 256 threads
__global__ void __launch_bounds__(256, 2) k_mlp1(
    const float* __restrict__ x,
    const float* __restrict__ wgate, const float* __restrict__ wup,
    const float* __restrict__ swg, const float* __restrict__ swu)
{
    __shared__ u64 xs[16 * HC];     // 32 KB
    __shared__ int s_toks[16];
    int b = blockIdx.x;
    int ih = b & 1;
    int eb = b >> 1;
    if (eb < EE) {
        int cnt = g_cnt[eb];
        int base = g_base[eb];
        const float* wg = wgate + (size_t)eb * HH * II;
        const float* wu = wup + (size_t)eb * HH * II;
        for (int off = 0; off < cnt; off += 16) {
            int nt = min(cnt - off, 16);
            __syncthreads();
            if (threadIdx.x < nt)
                s_toks[threadIdx.x] = g_pair_tok[base + off + threadIdx.x];
            float* act_base = g_act + (size_t)(base + off) * II;
            if (nt <= 8) mlp1_tile<8>(x, wg, wu, s_toks, nt, act_base, xs, ih);
            else         mlp1_tile<16>(x, wg, wu, s_toks, nt, act_base, xs, ih);
        }
    } else {
        int j = eb - EE;
        if (threadIdx.x < 16) s_toks[threadIdx.x] = j * 16 + threadIdx.x;
        __syncthreads();
        mlp1_tile<16>(x, swg, swu, s_toks, 16, g_act_sh + (size_t)j * 16 * II, xs, ih);
    }
}

// ---------------- down tile v2 ----------------
// 256 threads: hp = tid&127 (h-pair within 256-col chunk), is_ = tid>>7 (2 i-slices)
template <int TT>
__device__ __forceinline__ void down_tile(
    const float* __restrict__ wd, int h0,
    const int* s_toks, const float* s_w, int nt,
    float* __restrict__ out, u64* acts)
{
    const int tid = threadIdx.x;
    const int hp = tid & 127;
    const int is_ = tid >> 7;
    u64 acc[TT];
#pragma unroll
    for (int t2 = 0; t2 < TT; t2++) acc[t2] = 0ull;
    const float2* wd2 = (const float2*)wd;
    const int hcol = h0 / 2 + hp;
#pragma unroll 1
    for (int i = is_ * 128; i < is_ * 128 + 128; i += 4) {
        float2 wv[4];
#pragma unroll
        for (int u = 0; u < 4; u++)
            wv[u] = wd2[(size_t)(i + u) * (HH / 2) + hcol];
#pragma unroll
        for (int u = 0; u < 4; u++) {
            u64 wp = pack2(wv[u].x, wv[u].y);
#pragma unroll
            for (int t2 = 0; t2 < TT; t2++)
                acc[t2] = fma2(acts[t2 * II + i + u], wp, acc[t2]);
        }
    }
    // cross-slice reduce: layout [t2*256 + is_*128 + hp] (reuse acts smem)
    __syncthreads();
#pragma unroll
    for (int t2 = 0; t2 < TT; t2++) acts[t2 * 256 + is_ * 128 + hp] = acc[t2];
    __syncthreads();
    if (is_ == 0) {
#pragma unroll
        for (int t2 = 0; t2 < TT; t2++) {
            if (t2 < nt) {
                u64 s = add2(acts[t2 * 256 + hp], acts[t2 * 256 + 128 + hp]);
                float2 r = unpack2(s);
                float w = s_w[t2];
                int tok = s_toks[t2];
                atomicAdd(out + (size_t)tok * HH + h0 + 2 * hp,     w * r.x);
                atomicAdd(out + (size_t)tok * HH + h0 + 2 * hp + 1, w * r.y);
            }
        }
    }
}

// grid: (EE + 16 shared tiles) x 4 h-chunks; 256 threads
__global__ void __launch_bounds__(256, 2) k_down(
    const float* __restrict__ wdown, const float* __restrict__ swd,
    float* __restrict__ out)
{
    __shared__ u64 acts[16 * II];   // 32 KB
    __shared__ int s_toks[16];
    __shared__ float s_w[16];
    int b = blockIdx.x;
    int h0 = blockIdx.y * 256;
    if (b < EE) {
        int cnt = g_cnt[b];
        int base = g_base[b];
        const float* wd = wdown + (size_t)b * II * HH;
        for (int off = 0; off < cnt; off += 16) {
            int nt = min(cnt - off, 16);
            __syncthreads();
            if (threadIdx.x < nt) {
                s_toks[threadIdx.x] = g_pair_tok[base + off + threadIdx.x];
                s_w[threadIdx.x]   = g_pair_w[base + off + threadIdx.x];
            }
            for (int idx = threadIdx.x; idx < 16 * II; idx += 256) {
                int t2 = idx >> 8, i = idx & 255;
                float v = (t2 < nt) ? g_act[(size_t)(base + off + t2) * II + i] : 0.f;
                acts[idx] = pack2(v, v);
            }
            __syncthreads();
            if (nt <= 8) down_tile<8>(wd, h0, s_toks, s_w, nt, out, acts);
            else         down_tile<16>(wd, h0, s_toks, s_w, nt, out, acts);
        }
    } else {
        int j = b - EE;
        if (threadIdx.x < 16) {
            s_toks[threadIdx.x] = j * 16 + threadIdx.x;
            s_w[threadIdx.x] = 1.0f;
        }
        for (int idx = threadIdx.x; idx < 16 * II; idx += 256) {
            int t2 = idx >> 8, i = idx & 255;
            float v = g_act_sh[(size_t)(j * 16 + t2) * II + i];
            acts[idx] = pack2(v, v);
        }
        __syncthreads();
        down_tile<16>(swd, h0, s_toks, s_w, 16, out, acts);
    }
}

// ---------------- launch ----------------
extern "C" void kernel_launch(void* const* d_in, const int* in_sizes, int n_in,
                              void* d_out, int out_size)
{
    const float* x       = (const float*)d_in[0];  // [1,1,T,H]
    const float* gate_w  = (const float*)d_in[1];  // [E,H]
    const float* e_bias  = (const float*)d_in[2];  // [E]
    const float* w_gate  = (const float*)d_in[3];  // [E,H,I]
    const float* w_up    = (const float*)d_in[4];  // [E,H,I]
    const float* w_down  = (const float*)d_in[5];  // [E,I,H]
    const float* sw_gate = (const float*)d_in[6];  // [H,I]
    const float* sw_up   = (const float*)d_in[7];  // [H,I]
    const float* sw_down = (const float*)d_in[8];  // [I,H]
    float* out = (float*)d_out;                    // [1,1,T,H] fp32

    k_zero<<<(TT_T * HH + 255) / 256, 256>>>(out, TT_T * HH);
    k_gate<<<256, 256>>>(x, gate_w);
    k_route<<<1, 256>>>(e_bias);
    k_mlp1<<<EE * 2 + 32, 256>>>(x, w_gate, w_up, sw_gate, sw_up);
    k_down<<<dim3(EE + 16, 4), 256>>>(w_down, sw_down, out);
}